// round 8
// baseline (speedup 1.0000x reference)
#include <cuda_runtime.h>
#include <cuda_fp16.h>
#include <cstdint>

#define NNETS_MAX 3000000

// Per-net extremes, one 8-byte word per net:
//   g_ext[net].x = f16x2( xmax, max(-x) = -xmin )
//   g_ext[net].y = f16x2( ymax, max(-y) = -ymin )
// Identity/reset pattern: byte 0xFB -> each half = 0xFBFB = -65367 (finite f16),
// below any real coordinate => valid identity for max, settable by memset.
// word == 0xFBFBFBFB <=> net untouched.
__device__ uint2 g_ext[NNETS_MAX];

#define SENTINEL 0xFBFBFBFBu

// 64-bit vector reduction: componentwise max on 4 packed halves.
static __device__ __forceinline__ void red_max_v2f16x2(uint2* addr, unsigned w0, unsigned w1) {
    asm volatile("red.global.max.noftz.v2.f16x2 [%0], {%1, %2};"
                 :: "l"(addr), "r"(w0), "r"(w1) : "memory");
}

static __device__ __forceinline__ unsigned pack_pm(float v) {
    __half2 h = __floats2half2_rn(v, -v);  // lo = v, hi = -v
    return *reinterpret_cast<unsigned*>(&h);
}

// 4 pins per thread, ONE vector atomic per pin.
__global__ void pin_kernel4(const float4* __restrict__ x4,
                            const float4* __restrict__ y4,
                            const int4* __restrict__ net4,
                            int n4) {
    int i = blockIdx.x * blockDim.x + threadIdx.x;
    if (i >= n4) return;
    float4 x = __ldcs(x4 + i);
    float4 y = __ldcs(y4 + i);
    int4  nt = __ldcs(net4 + i);

    red_max_v2f16x2(g_ext + (unsigned)nt.x, pack_pm(x.x), pack_pm(y.x));
    red_max_v2f16x2(g_ext + (unsigned)nt.y, pack_pm(x.y), pack_pm(y.y));
    red_max_v2f16x2(g_ext + (unsigned)nt.z, pack_pm(x.z), pack_pm(y.z));
    red_max_v2f16x2(g_ext + (unsigned)nt.w, pack_pm(x.w), pack_pm(y.w));
}

__global__ void pin_kernel_tail(const float* __restrict__ pos,
                                const int* __restrict__ p2n,
                                int start, int npins) {
    int i = start + blockIdx.x * blockDim.x + threadIdx.x;
    if (i >= npins) return;
    red_max_v2f16x2(g_ext + (unsigned)__ldcs(p2n + i),
                    pack_pm(__ldcs(pos + i)),
                    pack_pm(__ldcs(pos + npins + i)));
}

// span of one packed word: lo + hi = vmax + (-vmin) = vmax - vmin
static __device__ __forceinline__ float span(unsigned w) {
    __half2 h = *reinterpret_cast<__half2*>(&w);
    float2 f = __half22float2(h);
    return f.x + f.y;
}

static __device__ __forceinline__ float net_term(unsigned ex, unsigned ey, int m) {
    float v = span(ex) + span(ey);
    return (m && ex != SENTINEL) ? v : 0.0f;
}

// mask is int32 (harness converts bool -> int32). Each thread: 16 nets,
// read-only, 12 independent 128-bit loads in flight.
__global__ void reduce_kernel(const int* __restrict__ mask,
                              float* __restrict__ out, int nnets) {
    int t = blockIdx.x * blockDim.x + threadIdx.x;
    int n0 = t * 16;
    float s = 0.0f;
    if (n0 + 15 < nnets) {
        uint4 e[8];
        #pragma unroll
        for (int k = 0; k < 8; k++)
            e[k] = __ldcs(reinterpret_cast<const uint4*>(g_ext + n0 + 2 * k));
        int4 m[4];
        #pragma unroll
        for (int k = 0; k < 4; k++)
            m[k] = __ldcs(reinterpret_cast<const int4*>(mask + n0 + 4 * k));
        #pragma unroll
        for (int k = 0; k < 4; k++) {
            s += net_term(e[2*k].x,   e[2*k].y,   m[k].x);
            s += net_term(e[2*k].z,   e[2*k].w,   m[k].y);
            s += net_term(e[2*k+1].x, e[2*k+1].y, m[k].z);
            s += net_term(e[2*k+1].z, e[2*k+1].w, m[k].w);
        }
    } else if (n0 < nnets) {
        for (int j = n0; j < nnets; j++) {
            uint2 ej = g_ext[j];
            s += net_term(ej.x, ej.y, mask[j]);
        }
    }
    // intra-warp reduce
    #pragma unroll
    for (int o = 16; o > 0; o >>= 1)
        s += __shfl_down_sync(0xFFFFFFFFu, s, o);
    __shared__ float ws[32];
    int lane = threadIdx.x & 31;
    int w = threadIdx.x >> 5;
    if (lane == 0) ws[w] = s;
    __syncthreads();
    if (w == 0) {
        int nw = (blockDim.x + 31) >> 5;
        s = (lane < nw) ? ws[lane] : 0.0f;
        #pragma unroll
        for (int o = 16; o > 0; o >>= 1)
            s += __shfl_down_sync(0xFFFFFFFFu, s, o);
        if (lane == 0) atomicAdd(out, s);
    }
}

extern "C" void kernel_launch(void* const* d_in, const int* in_sizes, int n_in,
                              void* d_out, int out_size) {
    const float* pos = (const float*)d_in[0];
    const int* p2n   = (const int*)d_in[1];
    const int* mask  = (const int*)d_in[2];
    float* out = (float*)d_out;

    const int npins = in_sizes[0] / 2;
    const int nnets = in_sizes[2];

    // reset: output accumulator to 0, scratch to the 0xFB identity pattern
    cudaMemsetAsync(out, 0, sizeof(float));
    void* ext_ptr = nullptr;
    cudaGetSymbolAddress(&ext_ptr, g_ext);
    cudaMemsetAsync(ext_ptr, 0xFB, (size_t)nnets * sizeof(uint2));

    // pin scatter (4-wide main + scalar tail)
    {
        int n4 = npins / 4;
        if (n4 > 0) {
            pin_kernel4<<<(n4 + 255) / 256, 256>>>(
                (const float4*)pos,
                (const float4*)(pos + npins),
                (const int4*)p2n,
                n4);
        }
        int rem = npins - n4 * 4;
        if (rem > 0) {
            pin_kernel_tail<<<(rem + 255) / 256, 256>>>(pos, p2n, n4 * 4, npins);
        }
    }

    // per-net HPWL + masked sum (16 nets per thread, read-only)
    {
        int nt = (nnets + 15) / 16;
        reduce_kernel<<<(nt + 255) / 256, 256>>>(mask, out, nnets);
    }
}

// round 9
// speedup vs baseline: 1.0651x; 1.0651x over previous
#include <cuda_runtime.h>
#include <cuda_fp16.h>
#include <cstdint>

#define NNETS_MAX 3000000

// Per-net extremes, one 8-byte word per net:
//   g_ext[net].x = f16x2( xmax,  ymax  )
//   g_ext[net].y = f16x2( -xmin, -ymin )
// Identity/reset pattern: byte 0xFB -> each half = 0xFBFB = -65367 (finite f16),
// below any real coordinate => valid identity for max, settable by memset.
// word == 0xFBFBFBFB <=> net untouched.
__device__ uint2 g_ext[NNETS_MAX];

#define SENTINEL 0xFBFBFBFBu

// 64-bit vector reduction: componentwise max on 4 packed halves.
static __device__ __forceinline__ void red_max_v2f16x2(uint2* addr, unsigned w0, unsigned w1) {
    asm volatile("red.global.max.noftz.v2.f16x2 [%0], {%1, %2};"
                 :: "l"(addr), "r"(w0), "r"(w1) : "memory");
}

// pack (x,y) once; negate the packed pair with one fp16 op
static __device__ __forceinline__ void pack_xy(float x, float y, unsigned& w0, unsigned& w1) {
    __half2 h = __floats2half2_rn(x, y);
    __half2 hn = __hneg2(h);
    w0 = *reinterpret_cast<unsigned*>(&h);
    w1 = *reinterpret_cast<unsigned*>(&hn);
}

// 4 pins per thread, ONE vector atomic per pin.
__global__ void pin_kernel4(const float4* __restrict__ x4,
                            const float4* __restrict__ y4,
                            const int4* __restrict__ net4,
                            int n4) {
    int i = blockIdx.x * blockDim.x + threadIdx.x;
    if (i >= n4) return;
    float4 x = __ldcs(x4 + i);
    float4 y = __ldcs(y4 + i);
    int4  nt = __ldcs(net4 + i);

    unsigned w0, w1;
    pack_xy(x.x, y.x, w0, w1); red_max_v2f16x2(g_ext + (unsigned)nt.x, w0, w1);
    pack_xy(x.y, y.y, w0, w1); red_max_v2f16x2(g_ext + (unsigned)nt.y, w0, w1);
    pack_xy(x.z, y.z, w0, w1); red_max_v2f16x2(g_ext + (unsigned)nt.z, w0, w1);
    pack_xy(x.w, y.w, w0, w1); red_max_v2f16x2(g_ext + (unsigned)nt.w, w0, w1);
}

__global__ void pin_kernel_tail(const float* __restrict__ pos,
                                const int* __restrict__ p2n,
                                int start, int npins) {
    int i = start + blockIdx.x * blockDim.x + threadIdx.x;
    if (i >= npins) return;
    unsigned w0, w1;
    pack_xy(__ldcs(pos + i), __ldcs(pos + npins + i), w0, w1);
    red_max_v2f16x2(g_ext + (unsigned)__ldcs(p2n + i), w0, w1);
}

// net term: (xmax + (-xmin)) + (ymax + (-ymin)) via one packed half2 add
static __device__ __forceinline__ float net_term(unsigned ex, unsigned ey, int m) {
    __half2 a = *reinterpret_cast<__half2*>(&ex);
    __half2 b = *reinterpret_cast<__half2*>(&ey);
    __half2 sp = __hadd2(a, b);          // (xmax-xmin, ymax-ymin)
    float2 f = __half22float2(sp);
    float v = f.x + f.y;
    return (m && ex != SENTINEL) ? v : 0.0f;
}

// mask is int32 (harness converts bool -> int32). Each thread: 8 nets,
// read-only (6 independent 128-bit loads in flight) — R7's best config.
__global__ void reduce_kernel(const int* __restrict__ mask,
                              float* __restrict__ out, int nnets) {
    int t = blockIdx.x * blockDim.x + threadIdx.x;
    int n0 = t * 8;
    float s = 0.0f;
    if (n0 + 7 < nnets) {
        uint4 e01 = __ldcs(reinterpret_cast<const uint4*>(g_ext + n0));
        uint4 e23 = __ldcs(reinterpret_cast<const uint4*>(g_ext + n0 + 2));
        uint4 e45 = __ldcs(reinterpret_cast<const uint4*>(g_ext + n0 + 4));
        uint4 e67 = __ldcs(reinterpret_cast<const uint4*>(g_ext + n0 + 6));
        int4  m0  = __ldcs(reinterpret_cast<const int4*>(mask + n0));
        int4  m1  = __ldcs(reinterpret_cast<const int4*>(mask + n0 + 4));
        s += net_term(e01.x, e01.y, m0.x);
        s += net_term(e01.z, e01.w, m0.y);
        s += net_term(e23.x, e23.y, m0.z);
        s += net_term(e23.z, e23.w, m0.w);
        s += net_term(e45.x, e45.y, m1.x);
        s += net_term(e45.z, e45.w, m1.y);
        s += net_term(e67.x, e67.y, m1.z);
        s += net_term(e67.z, e67.w, m1.w);
    } else if (n0 < nnets) {
        for (int j = n0; j < nnets; j++) {
            uint2 ej = g_ext[j];
            s += net_term(ej.x, ej.y, mask[j]);
        }
    }
    // intra-warp reduce
    #pragma unroll
    for (int o = 16; o > 0; o >>= 1)
        s += __shfl_down_sync(0xFFFFFFFFu, s, o);
    __shared__ float ws[32];
    int lane = threadIdx.x & 31;
    int w = threadIdx.x >> 5;
    if (lane == 0) ws[w] = s;
    __syncthreads();
    if (w == 0) {
        int nw = (blockDim.x + 31) >> 5;
        s = (lane < nw) ? ws[lane] : 0.0f;
        #pragma unroll
        for (int o = 16; o > 0; o >>= 1)
            s += __shfl_down_sync(0xFFFFFFFFu, s, o);
        if (lane == 0) atomicAdd(out, s);
    }
}

extern "C" void kernel_launch(void* const* d_in, const int* in_sizes, int n_in,
                              void* d_out, int out_size) {
    const float* pos = (const float*)d_in[0];
    const int* p2n   = (const int*)d_in[1];
    const int* mask  = (const int*)d_in[2];
    float* out = (float*)d_out;

    const int npins = in_sizes[0] / 2;
    const int nnets = in_sizes[2];

    // reset: output accumulator to 0, scratch to the 0xFB identity pattern
    cudaMemsetAsync(out, 0, sizeof(float));
    void* ext_ptr = nullptr;
    cudaGetSymbolAddress(&ext_ptr, g_ext);
    cudaMemsetAsync(ext_ptr, 0xFB, (size_t)nnets * sizeof(uint2));

    // pin scatter (4-wide main + scalar tail)
    {
        int n4 = npins / 4;
        if (n4 > 0) {
            pin_kernel4<<<(n4 + 255) / 256, 256>>>(
                (const float4*)pos,
                (const float4*)(pos + npins),
                (const int4*)p2n,
                n4);
        }
        int rem = npins - n4 * 4;
        if (rem > 0) {
            pin_kernel_tail<<<(rem + 255) / 256, 256>>>(pos, p2n, n4 * 4, npins);
        }
    }

    // per-net HPWL + masked sum (8 nets per thread, read-only)
    {
        int nt = (nnets + 7) / 8;
        reduce_kernel<<<(nt + 255) / 256, 256>>>(mask, out, nnets);
    }
}

// round 10
// speedup vs baseline: 1.0656x; 1.0005x over previous
#include <cuda_runtime.h>
#include <cuda_fp16.h>
#include <cstdint>

#define NNETS_MAX 3000000

// Per-net extremes, one 8-byte word per net:
//   g_ext[net].x = f16x2( xmax,  ymax  )
//   g_ext[net].y = f16x2( -xmin, -ymin )
// Identity/reset pattern: byte 0xFB -> each half = 0xFBFB = -65367 (finite f16),
// below any real coordinate => valid identity for max, settable by memset.
// word == 0xFBFBFBFB <=> net untouched.
__device__ uint2 g_ext[NNETS_MAX];

#define SENTINEL 0xFBFBFBFBu

// 64-bit vector reduction: componentwise max on 4 packed halves.
static __device__ __forceinline__ void red_max_v2f16x2(uint2* addr, unsigned w0, unsigned w1) {
    asm volatile("red.global.max.noftz.v2.f16x2 [%0], {%1, %2};"
                 :: "l"(addr), "r"(w0), "r"(w1) : "memory");
}

// pack (x,y) once; negate the packed pair with one fp16 op
static __device__ __forceinline__ void pack_xy(float x, float y, unsigned& w0, unsigned& w1) {
    __half2 h = __floats2half2_rn(x, y);
    __half2 hn = __hneg2(h);
    w0 = *reinterpret_cast<unsigned*>(&h);
    w1 = *reinterpret_cast<unsigned*>(&hn);
}

// 4 pins per thread, ONE vector atomic per pin.
__global__ void pin_kernel4(const float4* __restrict__ x4,
                            const float4* __restrict__ y4,
                            const int4* __restrict__ net4,
                            int n4) {
    int i = blockIdx.x * blockDim.x + threadIdx.x;
    if (i >= n4) return;
    float4 x = __ldcs(x4 + i);
    float4 y = __ldcs(y4 + i);
    int4  nt = __ldcs(net4 + i);

    unsigned w0, w1;
    pack_xy(x.x, y.x, w0, w1); red_max_v2f16x2(g_ext + (unsigned)nt.x, w0, w1);
    pack_xy(x.y, y.y, w0, w1); red_max_v2f16x2(g_ext + (unsigned)nt.y, w0, w1);
    pack_xy(x.z, y.z, w0, w1); red_max_v2f16x2(g_ext + (unsigned)nt.z, w0, w1);
    pack_xy(x.w, y.w, w0, w1); red_max_v2f16x2(g_ext + (unsigned)nt.w, w0, w1);
}

__global__ void pin_kernel_tail(const float* __restrict__ pos,
                                const int* __restrict__ p2n,
                                int start, int npins) {
    int i = start + blockIdx.x * blockDim.x + threadIdx.x;
    if (i >= npins) return;
    unsigned w0, w1;
    pack_xy(__ldcs(pos + i), __ldcs(pos + npins + i), w0, w1);
    red_max_v2f16x2(g_ext + (unsigned)__ldcs(p2n + i), w0, w1);
}

// net term: (xmax + (-xmin)) + (ymax + (-ymin)) via one packed half2 add
static __device__ __forceinline__ float net_term(unsigned ex, unsigned ey, int m) {
    __half2 a = *reinterpret_cast<__half2*>(&ex);
    __half2 b = *reinterpret_cast<__half2*>(&ey);
    __half2 sp = __hadd2(a, b);          // (xmax-xmin, ymax-ymin)
    float2 f = __half22float2(sp);
    float v = f.x + f.y;
    return (m && ex != SENTINEL) ? v : 0.0f;
}

// mask is int32 (harness converts bool -> int32). Each thread: 8 nets,
// read-only. Loads issued in two batches of 3 (software pipeline):
// lowers front-batched MLP (cross-CTA L1tex queue pressure) while the
// second batch's latency hides under the first batch's compute.
__global__ void __launch_bounds__(512)
reduce_kernel(const int* __restrict__ mask,
              float* __restrict__ out, int nnets) {
    int t = blockIdx.x * blockDim.x + threadIdx.x;
    int n0 = t * 8;
    float s = 0.0f;
    if (n0 + 7 < nnets) {
        // batch 0
        uint4 e01 = __ldcs(reinterpret_cast<const uint4*>(g_ext + n0));
        uint4 e23 = __ldcs(reinterpret_cast<const uint4*>(g_ext + n0 + 2));
        int4  m0  = __ldcs(reinterpret_cast<const int4*>(mask + n0));
        // batch 1 (issued before consuming batch 0 results)
        uint4 e45 = __ldcs(reinterpret_cast<const uint4*>(g_ext + n0 + 4));
        uint4 e67 = __ldcs(reinterpret_cast<const uint4*>(g_ext + n0 + 6));
        int4  m1  = __ldcs(reinterpret_cast<const int4*>(mask + n0 + 4));
        // consume batch 0
        s += net_term(e01.x, e01.y, m0.x);
        s += net_term(e01.z, e01.w, m0.y);
        s += net_term(e23.x, e23.y, m0.z);
        s += net_term(e23.z, e23.w, m0.w);
        // consume batch 1
        s += net_term(e45.x, e45.y, m1.x);
        s += net_term(e45.z, e45.w, m1.y);
        s += net_term(e67.x, e67.y, m1.z);
        s += net_term(e67.z, e67.w, m1.w);
    } else if (n0 < nnets) {
        for (int j = n0; j < nnets; j++) {
            uint2 ej = g_ext[j];
            s += net_term(ej.x, ej.y, mask[j]);
        }
    }
    // intra-warp reduce
    #pragma unroll
    for (int o = 16; o > 0; o >>= 1)
        s += __shfl_down_sync(0xFFFFFFFFu, s, o);
    __shared__ float ws[32];
    int lane = threadIdx.x & 31;
    int w = threadIdx.x >> 5;
    if (lane == 0) ws[w] = s;
    __syncthreads();
    if (w == 0) {
        int nw = (blockDim.x + 31) >> 5;
        s = (lane < nw) ? ws[lane] : 0.0f;
        #pragma unroll
        for (int o = 16; o > 0; o >>= 1)
            s += __shfl_down_sync(0xFFFFFFFFu, s, o);
        if (lane == 0) atomicAdd(out, s);
    }
}

extern "C" void kernel_launch(void* const* d_in, const int* in_sizes, int n_in,
                              void* d_out, int out_size) {
    const float* pos = (const float*)d_in[0];
    const int* p2n   = (const int*)d_in[1];
    const int* mask  = (const int*)d_in[2];
    float* out = (float*)d_out;

    const int npins = in_sizes[0] / 2;
    const int nnets = in_sizes[2];

    // reset: output accumulator to 0, scratch to the 0xFB identity pattern
    cudaMemsetAsync(out, 0, sizeof(float));
    void* ext_ptr = nullptr;
    cudaGetSymbolAddress(&ext_ptr, g_ext);
    cudaMemsetAsync(ext_ptr, 0xFB, (size_t)nnets * sizeof(uint2));

    // pin scatter (4-wide main + scalar tail)
    {
        int n4 = npins / 4;
        if (n4 > 0) {
            pin_kernel4<<<(n4 + 255) / 256, 256>>>(
                (const float4*)pos,
                (const float4*)(pos + npins),
                (const int4*)p2n,
                n4);
        }
        int rem = npins - n4 * 4;
        if (rem > 0) {
            pin_kernel_tail<<<(rem + 255) / 256, 256>>>(pos, p2n, n4 * 4, npins);
        }
    }

    // per-net HPWL + masked sum (8 nets per thread, pipelined loads)
    {
        int nt = (nnets + 7) / 8;
        reduce_kernel<<<(nt + 511) / 512, 512>>>(mask, out, nnets);
    }
}